// round 4
// baseline (speedup 1.0000x reference)
#include <cuda_runtime.h>
#include <math.h>

#define NB   8
#define QL   2048
#define KLEN 2048
#define ED   1024

// -------- single scratch arena (allocation-free __device__ global) --------
// Layout (floats):
//   [0,        16M)  Q          (later reused for `attended` — Q is dead by then)
//   [16M,      32M)  K
//   [32M,      48M)  V
//   [48M,      80M)  scores fallback (only if d_out has no room for attn)
#define OFF_Q 0ull
#define OFF_K 16777216ull
#define OFF_V 33554432ull
#define OFF_S 50331648ull
__device__ float g_scratch[83886080];   // 80M floats = 320 MB

#define TM  128
#define TN  128
#define TKK 16

// C = scale * A @ B(^T) (+ bias). A: MxK row-major. NT ? B: NxK : B: KxN.
// Any of A/Bm/C may be nullptr, in which case g_scratch + (aOff/bOff/cOff)
// is used instead (resolved in device code — no host symbol queries).
// blockIdx.z = batch with element strides sA/sB/sC.
template<bool NT>
__global__ __launch_bounds__(256, 2)
void gemm128(const float* __restrict__ A, size_t aOff,
             const float* __restrict__ Bm, size_t bOff,
             const float* __restrict__ bias,
             float* __restrict__ C, size_t cOff,
             int M, int N, int K, float scale,
             size_t sA, size_t sB, size_t sC)
{
    __shared__ float As[TKK][TM];
    __shared__ float Bs[TKK][TN];

    const float* Ap = A  ? A  : (const float*)(g_scratch + aOff);
    const float* Bp = Bm ? Bm : (const float*)(g_scratch + bOff);
    float*       Cp = C  ? C  : (g_scratch + cOff);

    const int tid = threadIdx.x;
    const int m0 = blockIdx.y * TM;
    const int n0 = blockIdx.x * TN;
    Ap += (size_t)blockIdx.z * sA;
    Bp += (size_t)blockIdx.z * sB;
    Cp += (size_t)blockIdx.z * sC;

    const int ty = tid >> 4;   // 0..15
    const int tx = tid & 15;   // 0..15

    float4 rA[2], rB[2];

    float acc[8][8];
#pragma unroll
    for (int i = 0; i < 8; i++)
#pragma unroll
        for (int j = 0; j < 8; j++) acc[i][j] = 0.f;

    // ---- prefetch tile 0 into registers ----
#pragma unroll
    for (int l = 0; l < 2; l++) {
        int idx = tid * 2 + l;
        rA[l] = *reinterpret_cast<const float4*>(
            Ap + (size_t)(m0 + (idx >> 2)) * K + (idx & 3) * 4);
        if (NT) {
            rB[l] = *reinterpret_cast<const float4*>(
                Bp + (size_t)(n0 + (idx >> 2)) * K + (idx & 3) * 4);
        } else {
            rB[l] = *reinterpret_cast<const float4*>(
                Bp + (size_t)(idx >> 5) * N + n0 + (idx & 31) * 4);
        }
    }

    for (int k0 = 0; k0 < K; k0 += TKK) {
        // ---- store prefetched registers to smem ----
#pragma unroll
        for (int l = 0; l < 2; l++) {
            int idx = tid * 2 + l;
            int row = idx >> 2;
            int c4  = idx & 3;
            As[c4 * 4 + 0][row] = rA[l].x;
            As[c4 * 4 + 1][row] = rA[l].y;
            As[c4 * 4 + 2][row] = rA[l].z;
            As[c4 * 4 + 3][row] = rA[l].w;
            if (NT) {
                Bs[c4 * 4 + 0][row] = rB[l].x;
                Bs[c4 * 4 + 1][row] = rB[l].y;
                Bs[c4 * 4 + 2][row] = rB[l].z;
                Bs[c4 * 4 + 3][row] = rB[l].w;
            } else {
                *reinterpret_cast<float4*>(&Bs[idx >> 5][(idx & 31) * 4]) = rB[l];
            }
        }
        __syncthreads();

        // ---- prefetch next tile (overlaps with compute below) ----
        const int kn = k0 + TKK;
        if (kn < K) {
#pragma unroll
            for (int l = 0; l < 2; l++) {
                int idx = tid * 2 + l;
                rA[l] = *reinterpret_cast<const float4*>(
                    Ap + (size_t)(m0 + (idx >> 2)) * K + kn + (idx & 3) * 4);
                if (NT) {
                    rB[l] = *reinterpret_cast<const float4*>(
                        Bp + (size_t)(n0 + (idx >> 2)) * K + kn + (idx & 3) * 4);
                } else {
                    rB[l] = *reinterpret_cast<const float4*>(
                        Bp + (size_t)(kn + (idx >> 5)) * N + n0 + (idx & 31) * 4);
                }
            }
        }

        // ---- compute on current smem tile ----
#pragma unroll
        for (int kt = 0; kt < TKK; kt++) {
            float a[8], b[8];
            *reinterpret_cast<float4*>(&a[0]) = *reinterpret_cast<const float4*>(&As[kt][ty * 8]);
            *reinterpret_cast<float4*>(&a[4]) = *reinterpret_cast<const float4*>(&As[kt][ty * 8 + 4]);
            *reinterpret_cast<float4*>(&b[0]) = *reinterpret_cast<const float4*>(&Bs[kt][tx * 8]);
            *reinterpret_cast<float4*>(&b[4]) = *reinterpret_cast<const float4*>(&Bs[kt][tx * 8 + 4]);
#pragma unroll
            for (int i = 0; i < 8; i++)
#pragma unroll
                for (int j = 0; j < 8; j++)
                    acc[i][j] = fmaf(a[i], b[j], acc[i][j]);
        }
        __syncthreads();
    }

    // ---- epilogue ----
#pragma unroll
    for (int i = 0; i < 8; i++) {
        int m = m0 + ty * 8 + i;
#pragma unroll
        for (int j = 0; j < 8; j += 4) {
            int n = n0 + tx * 8 + j;
            float4 r;
            r.x = acc[i][j + 0] * scale;
            r.y = acc[i][j + 1] * scale;
            r.z = acc[i][j + 2] * scale;
            r.w = acc[i][j + 3] * scale;
            if (bias) {
                const float4 bv = *reinterpret_cast<const float4*>(bias + n);
                r.x += bv.x; r.y += bv.y; r.z += bv.z; r.w += bv.w;
            }
            *reinterpret_cast<float4*>(Cp + (size_t)m * N + n) = r;
        }
    }
}

// Row-wise masked softmax in place. One block per (b,q) row; KLEN=2048, 256 thr x 8.
// att==nullptr -> operate on g_scratch + attOff.
__global__ __launch_bounds__(256)
void softmax_mask_kernel(float* att, size_t attOff, const int* __restrict__ mask)
{
    float* base = att ? att : (g_scratch + attOff);
    const size_t row = blockIdx.x;
    float* p = base + row * KLEN;
    const int* mp = mask + row * KLEN;
    const int t = threadIdx.x;
    __shared__ float red[256];

    float v[8];
    float mx = -INFINITY;
#pragma unroll
    for (int i = 0; i < 8; i++) {
        int c = t + i * 256;
        float x = p[c];
        x = mp[c] ? x : -INFINITY;
        v[i] = x;
        mx = fmaxf(mx, x);
    }
    red[t] = mx; __syncthreads();
    for (int s = 128; s > 0; s >>= 1) {
        if (t < s) red[t] = fmaxf(red[t], red[t + s]);
        __syncthreads();
    }
    mx = red[0];
    __syncthreads();

    float sum = 0.f;
#pragma unroll
    for (int i = 0; i < 8; i++) {
        float e = __expf(v[i] - mx);
        v[i] = e;
        sum += e;
    }
    red[t] = sum; __syncthreads();
    for (int s = 128; s > 0; s >>= 1) {
        if (t < s) red[t] += red[t + s];
        __syncthreads();
    }
    const float inv = 1.f / red[0];
#pragma unroll
    for (int i = 0; i < 8; i++)
        p[t + i * 256] = v[i] * inv;
}

extern "C" void kernel_launch(void* const* d_in, const int* in_sizes, int n_in,
                              void* d_out, int out_size)
{
    const float* query = (const float*)d_in[0];
    const float* keyv  = (const float*)d_in[1];
    const int*   mask  = (const int*)  d_in[2];
    const float* Wq = (const float*)d_in[3];
    const float* bq = (const float*)d_in[4];
    const float* Wk = (const float*)d_in[5];
    const float* bk = (const float*)d_in[6];
    const float* Wv = (const float*)d_in[7];
    const float* bv = (const float*)d_in[8];
    const float* Wo = (const float*)d_in[9];
    const float* bo = (const float*)d_in[10];

    float* out = (float*)d_out;
    const size_t out_elems = (size_t)NB * QL * ED;          // 16,777,216

    // attn lives in d_out after `out` when the harness expects both outputs,
    // otherwise in the scratch arena.
    const bool attn_in_out = ((size_t)out_size > out_elems);
    float* attn_ptr = attn_in_out ? (out + out_elems) : nullptr;  // nullptr -> scratch OFF_S

    const int M_ALL = NB * QL;  // 16384
    const float scale = 1.0f / 32.0f; // 1/sqrt(1024)

    dim3 gProj(ED / TN, M_ALL / TM, 1);          // (8, 128, 1)
    dim3 gScore(KLEN / TN, QL / TM, NB);         // (16, 16, 8)
    dim3 gAV(ED / TN, QL / TM, NB);              // (8, 16, 8)

    // 1-3: projections (C -> scratch Q/K/V)
    gemm128<false><<<gProj, 256>>>(query, 0, Wq, 0, bq, nullptr, OFF_Q,
                                   M_ALL, ED, ED, 1.0f, 0, 0, 0);
    gemm128<false><<<gProj, 256>>>(keyv, 0, Wk, 0, bk, nullptr, OFF_K,
                                   M_ALL, ED, ED, 1.0f, 0, 0, 0);
    gemm128<false><<<gProj, 256>>>(keyv, 0, Wv, 0, bv, nullptr, OFF_V,
                                   M_ALL, ED, ED, 1.0f, 0, 0, 0);

    // 4: scores = scale * Q @ K^T (per batch) -> attn destination
    gemm128<true><<<gScore, 256>>>(nullptr, OFF_Q, nullptr, OFF_K, nullptr,
                                   attn_ptr, OFF_S,
                                   QL, KLEN, ED, scale,
                                   (size_t)QL * ED, (size_t)KLEN * ED,
                                   (size_t)QL * KLEN);

    // 5: masked softmax in place
    softmax_mask_kernel<<<NB * QL, 256>>>(attn_ptr, OFF_S, mask);

    // 6: attended = attn @ V (per batch) -> reuse Q region (Q is dead now)
    gemm128<false><<<gAV, 256>>>(attn_ptr, OFF_S, nullptr, OFF_V, nullptr,
                                 nullptr, OFF_Q,
                                 QL, ED, KLEN, 1.0f,
                                 (size_t)QL * KLEN, (size_t)KLEN * ED,
                                 (size_t)QL * ED);

    // 7: out = attended @ Wo + bo
    gemm128<false><<<gProj, 256>>>(nullptr, OFF_Q, Wo, 0, bo, out, 0,
                                   M_ALL, ED, ED, 1.0f, 0, 0, 0);
}

// round 6
// speedup vs baseline: 6.0234x; 6.0234x over previous
#include <cuda_runtime.h>
#include <math.h>
#include <stdint.h>

#define NB   8
#define QL   2048
#define KLEN 2048
#define ED   1024

// ---------------- scratch arena (floats) ----------------
#define OFF_Q   0ull
#define OFF_K   16777216ull
#define OFF_V   33554432ull
#define OFF_VT  50331648ull
#define OFF_WQ  67108864ull
#define OFF_WK  68157440ull
#define OFF_WV  69206016ull
#define OFF_WO  70254592ull
#define OFF_S   71303168ull
__device__ float g_scratch[104857600ull];   // 400 MB

// ---------------- helpers ----------------
__device__ __forceinline__ uint32_t smem_u32(const void* p) {
    uint32_t a;
    asm("{ .reg .u64 t; cvta.to.shared.u64 t, %1; cvt.u32.u64 %0, t; }" : "=r"(a) : "l"(p));
    return a;
}
__device__ __forceinline__ uint32_t f2tf32(float f) {
    uint32_t u;
    asm("cvt.rna.tf32.f32 %0, %1;" : "=r"(u) : "f"(f));
    return u;
}
__device__ __forceinline__ void cp16(uint32_t s, const void* g) {
    asm volatile("cp.async.cg.shared.global [%0], [%1], 16;" :: "r"(s), "l"(g));
}
__device__ __forceinline__ void mma_tf32(float* d, const uint32_t* a, const uint32_t* b) {
    asm volatile(
        "mma.sync.aligned.m16n8k8.row.col.f32.tf32.tf32.f32 "
        "{%0,%1,%2,%3}, {%4,%5,%6,%7}, {%8,%9}, {%0,%1,%2,%3};"
        : "+f"(d[0]), "+f"(d[1]), "+f"(d[2]), "+f"(d[3])
        : "r"(a[0]), "r"(a[1]), "r"(a[2]), "r"(a[3]), "r"(b[0]), "r"(b[1]));
}

// ---------------- tf32 mma.sync GEMM ----------------
// C[M,N] = scale * A[M,K] @ B[N,K]^T (+bias[n]); A and B both K-major row-major.
// nullptr operand -> g_scratch + offset. blockIdx.z batches with strides.
#define BM 128
#define BN 128
#define BK 32
#define PAD 36                       // floats per smem row: banks 4r+t conflict-free
#define TILE_F (128 * PAD)           // 4608 floats per operand tile
#define SMEM_FLOATS (4 * TILE_F)     // A0 B0 A1 B1
#define SMEM_BYTES  (SMEM_FLOATS * 4)  // 73728

__global__ void __launch_bounds__(256, 2)
gemm_mma(const float* A, size_t aOff, const float* B, size_t bOff,
         const float* bias, float* C, size_t cOff,
         int M, int N, int Kd, float scale,
         size_t sA, size_t sB, size_t sC)
{
    extern __shared__ float sm[];
    const float* Ap = A ? A : (const float*)(g_scratch + aOff);
    const float* Bp = B ? B : (const float*)(g_scratch + bOff);
    float*       Cp = C ? C : (g_scratch + cOff);
    Ap += (size_t)blockIdx.z * sA;
    Bp += (size_t)blockIdx.z * sB;
    Cp += (size_t)blockIdx.z * sC;

    const int tid  = threadIdx.x;
    const int lane = tid & 31;
    const int wid  = tid >> 5;
    const int wm   = wid >> 2;        // 0..1  (m warp row)
    const int wn   = wid & 3;         // 0..3  (n warp col)
    const int m0   = blockIdx.y * BM;
    const int n0   = blockIdx.x * BN;
    const uint32_t sbase = smem_u32(sm);

    float acc[4][4][4];
#pragma unroll
    for (int a = 0; a < 4; a++)
#pragma unroll
        for (int b = 0; b < 4; b++)
#pragma unroll
            for (int c = 0; c < 4; c++) acc[a][b][c] = 0.f;

    // smem tile layout: buf0: A@0, B@TILE_F ; buf1: A@2*TILE_F, B@3*TILE_F
    auto issue_tile = [&](int k0, int bufsel) {
        const uint32_t aB = sbase + (bufsel ? 2u * TILE_F * 4u : 0u);
        const uint32_t bB = sbase + (bufsel ? 3u * TILE_F * 4u : TILE_F * 4u);
#pragma unroll
        for (int j = 0; j < 4; j++) {
            int f  = tid + j * 256;       // 0..1023
            int r  = f >> 3;              // 0..127
            int c4 = f & 7;               // 0..7  (16B chunk)
            uint32_t so = (uint32_t)(r * PAD + c4 * 4) * 4u;
            cp16(aB + so, Ap + (size_t)(m0 + r) * Kd + k0 + c4 * 4);
            cp16(bB + so, Bp + (size_t)(n0 + r) * Kd + k0 + c4 * 4);
        }
        asm volatile("cp.async.commit_group;" ::: "memory");
    };

    issue_tile(0, 0);
    const int NT = Kd / BK;

    for (int i = 0; i < NT; i++) {
        const int buf = i & 1;
        if (i + 1 < NT) {
            issue_tile((i + 1) * BK, buf ^ 1);
            asm volatile("cp.async.wait_group 1;" ::: "memory");
        } else {
            asm volatile("cp.async.wait_group 0;" ::: "memory");
        }
        __syncthreads();

        const float* As = sm + (buf ? 2 * TILE_F : 0);
        const float* Bs = sm + (buf ? 3 * TILE_F : TILE_F);

#pragma unroll
        for (int s = 0; s < 4; s++) {               // 4 x k8 = BK 32
            uint32_t af[4][4], bf[4][2];
#pragma unroll
            for (int mt = 0; mt < 4; mt++) {
                const int row = wm * 64 + mt * 16 + (lane >> 2);
                const float* p = As + row * PAD + s * 8 + (lane & 3);
                af[mt][0] = f2tf32(p[0]);
                af[mt][1] = f2tf32(p[8 * PAD]);
                af[mt][2] = f2tf32(p[4]);
                af[mt][3] = f2tf32(p[8 * PAD + 4]);
            }
#pragma unroll
            for (int nt = 0; nt < 4; nt++) {
                const int nr = wn * 32 + nt * 8 + (lane >> 2);
                const float* p = Bs + nr * PAD + s * 8 + (lane & 3);
                bf[nt][0] = f2tf32(p[0]);
                bf[nt][1] = f2tf32(p[4]);
            }
#pragma unroll
            for (int mt = 0; mt < 4; mt++)
#pragma unroll
                for (int nt = 0; nt < 4; nt++)
                    mma_tf32(acc[mt][nt], af[mt], bf[nt]);
        }
        __syncthreads();
    }

    // ---------------- epilogue: registers -> gmem directly ----------------
#pragma unroll
    for (int mt = 0; mt < 4; mt++) {
        const int m = m0 + wm * 64 + mt * 16 + (lane >> 2);
#pragma unroll
        for (int nt = 0; nt < 4; nt++) {
            const int n = n0 + wn * 32 + nt * 8 + (lane & 3) * 2;
            float bx = 0.f, by = 0.f;
            if (bias) {
                const float2 bb = *reinterpret_cast<const float2*>(bias + n);
                bx = bb.x; by = bb.y;
            }
            float2 v0, v1;
            v0.x = acc[mt][nt][0] * scale + bx;
            v0.y = acc[mt][nt][1] * scale + by;
            v1.x = acc[mt][nt][2] * scale + bx;
            v1.y = acc[mt][nt][3] * scale + by;
            *reinterpret_cast<float2*>(Cp + (size_t)m * N + n) = v0;
            *reinterpret_cast<float2*>(Cp + (size_t)(m + 8) * N + n) = v1;
        }
    }
}

// ---------------- transpose: out[Cc,R] = in[R,Cc]^T ----------------
__global__ void __launch_bounds__(256)
transpose_mat(const float* in, size_t inOff, float* out, size_t outOff,
              int R, int Cc, size_t sIn, size_t sOut)
{
    __shared__ float t[32][33];
    const float* ip = in ? in : (const float*)(g_scratch + inOff);
    float*       op = out ? out : (g_scratch + outOff);
    ip += (size_t)blockIdx.z * sIn;
    op += (size_t)blockIdx.z * sOut;
    const int c0 = blockIdx.x * 32, r0 = blockIdx.y * 32;
    const int tx = threadIdx.x & 31, ty = threadIdx.x >> 5;
#pragma unroll
    for (int i = 0; i < 4; i++)
        t[ty + i * 8][tx] = ip[(size_t)(r0 + ty + i * 8) * Cc + c0 + tx];
    __syncthreads();
#pragma unroll
    for (int i = 0; i < 4; i++)
        op[(size_t)(c0 + ty + i * 8) * R + r0 + tx] = t[tx][ty + i * 8];
}

// ---------------- masked row softmax (in place) ----------------
__global__ void __launch_bounds__(256)
softmax_mask_kernel(float* att, size_t attOff, const int* __restrict__ mask)
{
    float* base = att ? att : (g_scratch + attOff);
    const size_t row = blockIdx.x;
    float* p = base + row * KLEN;
    const int* mp = mask + row * KLEN;
    const int t = threadIdx.x;
    __shared__ float red[256];

    float v[8];
    float mx = -INFINITY;
#pragma unroll
    for (int i = 0; i < 8; i++) {
        int c = t + i * 256;
        float x = p[c];
        x = mp[c] ? x : -INFINITY;
        v[i] = x;
        mx = fmaxf(mx, x);
    }
    red[t] = mx; __syncthreads();
    for (int s = 128; s > 0; s >>= 1) {
        if (t < s) red[t] = fmaxf(red[t], red[t + s]);
        __syncthreads();
    }
    mx = red[0];
    __syncthreads();

    float sum = 0.f;
#pragma unroll
    for (int i = 0; i < 8; i++) { float e = __expf(v[i] - mx); v[i] = e; sum += e; }
    red[t] = sum; __syncthreads();
    for (int s = 128; s > 0; s >>= 1) {
        if (t < s) red[t] += red[t + s];
        __syncthreads();
    }
    const float inv = 1.f / red[0];
#pragma unroll
    for (int i = 0; i < 8; i++) p[t + i * 256] = v[i] * inv;
}

// ---------------- launch ----------------
extern "C" void kernel_launch(void* const* d_in, const int* in_sizes, int n_in,
                              void* d_out, int out_size)
{
    const float* query = (const float*)d_in[0];
    const float* keyv  = (const float*)d_in[1];
    const int*   mask  = (const int*)  d_in[2];
    const float* Wq = (const float*)d_in[3];
    const float* bq = (const float*)d_in[4];
    const float* Wk = (const float*)d_in[5];
    const float* bk = (const float*)d_in[6];
    const float* Wv = (const float*)d_in[7];
    const float* bv = (const float*)d_in[8];
    const float* Wo = (const float*)d_in[9];
    const float* bo = (const float*)d_in[10];

    float* out = (float*)d_out;
    const size_t out_elems = (size_t)NB * QL * ED;
    const bool attn_in_out = ((size_t)out_size > out_elems);
    float* attn_ptr = attn_in_out ? (out + out_elems) : nullptr;  // nullptr -> OFF_S

    static bool attr_set = false;
    if (!attr_set) {
        cudaFuncSetAttribute(gemm_mma, cudaFuncAttributeMaxDynamicSharedMemorySize, SMEM_BYTES);
        attr_set = true;
    }

    const int M_ALL = NB * QL;           // 16384
    const float scale = 1.0f / 32.0f;    // 1/sqrt(1024)

    dim3 tposeW(ED / 32, ED / 32, 1);
    dim3 tposeV(ED / 32, KLEN / 32, NB);
    dim3 gProj (ED / BN,   M_ALL / BM, 1);           // (8, 128, 1)
    dim3 gScore(KLEN / BN, QL / BM,    NB);          // (16, 16, 8)
    dim3 gAV   (ED / BN,   QL / BM,    NB);          // (8, 16, 8)

    // 0: weight transposes -> K-major B operands
    transpose_mat<<<tposeW, 256>>>(Wq, 0, nullptr, OFF_WQ, ED, ED, 0, 0);
    transpose_mat<<<tposeW, 256>>>(Wk, 0, nullptr, OFF_WK, ED, ED, 0, 0);
    transpose_mat<<<tposeW, 256>>>(Wv, 0, nullptr, OFF_WV, ED, ED, 0, 0);
    transpose_mat<<<tposeW, 256>>>(Wo, 0, nullptr, OFF_WO, ED, ED, 0, 0);

    // 1-3: projections
    gemm_mma<<<gProj, 256, SMEM_BYTES>>>(query, 0, nullptr, OFF_WQ, bq, nullptr, OFF_Q,
                                         M_ALL, ED, ED, 1.0f, 0, 0, 0);
    gemm_mma<<<gProj, 256, SMEM_BYTES>>>(keyv, 0, nullptr, OFF_WK, bk, nullptr, OFF_K,
                                         M_ALL, ED, ED, 1.0f, 0, 0, 0);
    gemm_mma<<<gProj, 256, SMEM_BYTES>>>(keyv, 0, nullptr, OFF_WV, bv, nullptr, OFF_V,
                                         M_ALL, ED, ED, 1.0f, 0, 0, 0);

    // V^T for attn@V
    transpose_mat<<<tposeV, 256>>>(nullptr, OFF_V, nullptr, OFF_VT,
                                   KLEN, ED, (size_t)KLEN * ED, (size_t)ED * KLEN);

    // 4: scores = scale * Q @ K^T
    gemm_mma<<<gScore, 256, SMEM_BYTES>>>(nullptr, OFF_Q, nullptr, OFF_K, nullptr,
                                          attn_ptr, OFF_S,
                                          QL, KLEN, ED, scale,
                                          (size_t)QL * ED, (size_t)KLEN * ED,
                                          (size_t)QL * KLEN);

    // 5: masked softmax in place
    softmax_mask_kernel<<<NB * QL, 256>>>(attn_ptr, OFF_S, mask);

    // 6: attended = attn @ V  -> reuse OFF_Q (Q dead)
    gemm_mma<<<gAV, 256, SMEM_BYTES>>>(attn_ptr, OFF_S, nullptr, OFF_VT, nullptr,
                                       nullptr, OFF_Q,
                                       QL, ED, KLEN, 1.0f,
                                       (size_t)QL * KLEN, (size_t)ED * KLEN,
                                       (size_t)QL * ED);

    // 7: out = attended @ Wo + bo
    gemm_mma<<<gProj, 256, SMEM_BYTES>>>(nullptr, OFF_Q, nullptr, OFF_WO, bo, out, 0,
                                         M_ALL, ED, ED, 1.0f, 0, 0, 0);
}

// round 7
// speedup vs baseline: 6.5527x; 1.0879x over previous
#include <cuda_runtime.h>
#include <math.h>
#include <stdint.h>

#define NB   8
#define QL   2048
#define KLEN 2048
#define ED   1024

// ---------------- scratch arena (floats) ----------------
#define OFF_Q   0ull
#define OFF_K   16777216ull
#define OFF_V   33554432ull
#define OFF_VT  50331648ull
#define OFF_WQ  67108864ull
#define OFF_WK  68157440ull
#define OFF_WV  69206016ull
#define OFF_WO  70254592ull
#define OFF_S   71303168ull
__device__ float g_scratch[104857600ull];   // 400 MB

// ---------------- helpers ----------------
__device__ __forceinline__ uint32_t smem_u32(const void* p) {
    uint32_t a;
    asm("{ .reg .u64 t; cvta.to.shared.u64 t, %1; cvt.u32.u64 %0, t; }" : "=r"(a) : "l"(p));
    return a;
}
__device__ __forceinline__ uint32_t f2tf32(float f) {
    uint32_t u;
    asm("cvt.rna.tf32.f32 %0, %1;" : "=r"(u) : "f"(f));
    return u;
}
__device__ __forceinline__ void cp16(uint32_t s, const void* g) {
    asm volatile("cp.async.cg.shared.global [%0], [%1], 16;" :: "r"(s), "l"(g));
}
__device__ __forceinline__ void mma_tf32(float* d, const uint32_t* a, const uint32_t* b) {
    asm volatile(
        "mma.sync.aligned.m16n8k8.row.col.f32.tf32.tf32.f32 "
        "{%0,%1,%2,%3}, {%4,%5,%6,%7}, {%8,%9}, {%0,%1,%2,%3};"
        : "+f"(d[0]), "+f"(d[1]), "+f"(d[2]), "+f"(d[3])
        : "r"(a[0]), "r"(a[1]), "r"(a[2]), "r"(a[3]), "r"(b[0]), "r"(b[1]));
}

// ---------------- tf32 mma.sync GEMM ----------------
// C[M,N] = scale * A[M,K] @ B[N,K]^T (+bias[n]); A,B K-major row-major.
// CA/CB: apply cvt.rna.tf32 on operand load (0 if producer pre-rounded).
// RC: round C to tf32 on store (for GEMM-only consumers).
#define BM 128
#define BN 128
#define BK 32
#define PAD 36                        // banks (36r+c)&31 = (4r+c)&31: conflict-free
#define TILE_F (128 * PAD)
#define SMEM_BYTES (4 * TILE_F * 4)   // A0 B0 A1 B1 = 73728 B

template<int CA, int CB, int RC>
__global__ void __launch_bounds__(128, 2)
gemm_mma(const float* A, size_t aOff, const float* B, size_t bOff,
         const float* bias, float* C, size_t cOff,
         int M, int N, int Kd, float scale,
         size_t sA, size_t sB, size_t sC)
{
    extern __shared__ float sm[];
    const float* Ap = A ? A : (const float*)(g_scratch + aOff);
    const float* Bp = B ? B : (const float*)(g_scratch + bOff);
    float*       Cp = C ? C : (g_scratch + cOff);
    Ap += (size_t)blockIdx.z * sA;
    Bp += (size_t)blockIdx.z * sB;
    Cp += (size_t)blockIdx.z * sC;

    const int tid  = threadIdx.x;
    const int lane = tid & 31;
    const int wid  = tid >> 5;        // 0..3
    const int wm   = wid >> 1;        // 0..1
    const int wn   = wid & 1;         // 0..1
    const int m0   = blockIdx.y * BM;
    const int n0   = blockIdx.x * BN;
    const uint32_t sbase = smem_u32(sm);

    float acc[4][8][4];
#pragma unroll
    for (int a = 0; a < 4; a++)
#pragma unroll
        for (int b = 0; b < 8; b++)
#pragma unroll
            for (int c = 0; c < 4; c++) acc[a][b][c] = 0.f;

    auto issue_tile = [&](int k0, int bufsel) {
        const uint32_t aB = sbase + (bufsel ? 2u * TILE_F * 4u : 0u);
        const uint32_t bB = sbase + (bufsel ? 3u * TILE_F * 4u : TILE_F * 4u);
#pragma unroll
        for (int j = 0; j < 8; j++) {
            int f  = tid + j * 128;       // 0..1023
            int r  = f >> 3;              // 0..127
            int c4 = f & 7;               // 0..7
            uint32_t so = (uint32_t)(r * PAD + c4 * 4) * 4u;
            cp16(aB + so, Ap + (size_t)(m0 + r) * Kd + k0 + c4 * 4);
            cp16(bB + so, Bp + (size_t)(n0 + r) * Kd + k0 + c4 * 4);
        }
        asm volatile("cp.async.commit_group;" ::: "memory");
    };

    issue_tile(0, 0);
    const int NT = Kd / BK;

    for (int i = 0; i < NT; i++) {
        const int buf = i & 1;
        if (i + 1 < NT) {
            issue_tile((i + 1) * BK, buf ^ 1);
            asm volatile("cp.async.wait_group 1;" ::: "memory");
        } else {
            asm volatile("cp.async.wait_group 0;" ::: "memory");
        }
        __syncthreads();

        const float* As = sm + (buf ? 2 * TILE_F : 0);
        const float* Bs = sm + (buf ? 3 * TILE_F : TILE_F);

#pragma unroll
        for (int s = 0; s < 4; s++) {               // 4 x k8 = BK
            uint32_t af[4][4], bf[8][2];
#pragma unroll
            for (int mt = 0; mt < 4; mt++) {
                const int row = wm * 64 + mt * 16 + (lane >> 2);
                const float* p = As + row * PAD + s * 8 + (lane & 3);
                if (CA) {
                    af[mt][0] = f2tf32(p[0]);
                    af[mt][1] = f2tf32(p[8 * PAD]);
                    af[mt][2] = f2tf32(p[4]);
                    af[mt][3] = f2tf32(p[8 * PAD + 4]);
                } else {
                    af[mt][0] = __float_as_uint(p[0]);
                    af[mt][1] = __float_as_uint(p[8 * PAD]);
                    af[mt][2] = __float_as_uint(p[4]);
                    af[mt][3] = __float_as_uint(p[8 * PAD + 4]);
                }
            }
#pragma unroll
            for (int nt = 0; nt < 8; nt++) {
                const int nr = wn * 64 + nt * 8 + (lane >> 2);
                const float* p = Bs + nr * PAD + s * 8 + (lane & 3);
                if (CB) {
                    bf[nt][0] = f2tf32(p[0]);
                    bf[nt][1] = f2tf32(p[4]);
                } else {
                    bf[nt][0] = __float_as_uint(p[0]);
                    bf[nt][1] = __float_as_uint(p[4]);
                }
            }
#pragma unroll
            for (int mt = 0; mt < 4; mt++)
#pragma unroll
                for (int nt = 0; nt < 8; nt++)
                    mma_tf32(acc[mt][nt], af[mt], bf[nt]);
        }
        __syncthreads();
    }

    // ---------------- epilogue ----------------
#pragma unroll
    for (int mt = 0; mt < 4; mt++) {
        const int m = m0 + wm * 64 + mt * 16 + (lane >> 2);
#pragma unroll
        for (int nt = 0; nt < 8; nt++) {
            const int n = n0 + wn * 64 + nt * 8 + (lane & 3) * 2;
            float bx = 0.f, by = 0.f;
            if (bias) {
                const float2 bb = *reinterpret_cast<const float2*>(bias + n);
                bx = bb.x; by = bb.y;
            }
            float2 v0, v1;
            v0.x = acc[mt][nt][0] * scale + bx;
            v0.y = acc[mt][nt][1] * scale + by;
            v1.x = acc[mt][nt][2] * scale + bx;
            v1.y = acc[mt][nt][3] * scale + by;
            if (RC) {
                v0.x = __uint_as_float(f2tf32(v0.x));
                v0.y = __uint_as_float(f2tf32(v0.y));
                v1.x = __uint_as_float(f2tf32(v1.x));
                v1.y = __uint_as_float(f2tf32(v1.y));
            }
            *reinterpret_cast<float2*>(Cp + (size_t)m * N + n) = v0;
            *reinterpret_cast<float2*>(Cp + (size_t)(m + 8) * N + n) = v1;
        }
    }
}

// ---------------- transpose: out[Cc,R] = in[R,Cc]^T (optional tf32 round) ----
__global__ void __launch_bounds__(256)
transpose_mat(const float* in, size_t inOff, float* out, size_t outOff,
              int R, int Cc, size_t sIn, size_t sOut, int doRound)
{
    __shared__ float t[32][33];
    const float* ip = in ? in : (const float*)(g_scratch + inOff);
    float*       op = out ? out : (g_scratch + outOff);
    ip += (size_t)blockIdx.z * sIn;
    op += (size_t)blockIdx.z * sOut;
    const int c0 = blockIdx.x * 32, r0 = blockIdx.y * 32;
    const int tx = threadIdx.x & 31, ty = threadIdx.x >> 5;
#pragma unroll
    for (int i = 0; i < 4; i++) {
        float v = ip[(size_t)(r0 + ty + i * 8) * Cc + c0 + tx];
        if (doRound) v = __uint_as_float(f2tf32(v));
        t[ty + i * 8][tx] = v;
    }
    __syncthreads();
#pragma unroll
    for (int i = 0; i < 4; i++)
        op[(size_t)(c0 + ty + i * 8) * R + r0 + tx] = t[tx][ty + i * 8];
}

// ---------------- masked row softmax (in place) ----------------
__global__ void __launch_bounds__(256)
softmax_mask_kernel(float* att, size_t attOff, const int* __restrict__ mask)
{
    float* base = att ? att : (g_scratch + attOff);
    const size_t row = blockIdx.x;
    float* p = base + row * KLEN;
    const int* mp = mask + row * KLEN;
    const int t = threadIdx.x;
    __shared__ float red[256];

    float v[8];
    float mx = -INFINITY;
#pragma unroll
    for (int i = 0; i < 8; i++) {
        int c = t + i * 256;
        float x = p[c];
        x = mp[c] ? x : -INFINITY;
        v[i] = x;
        mx = fmaxf(mx, x);
    }
    red[t] = mx; __syncthreads();
    for (int s = 128; s > 0; s >>= 1) {
        if (t < s) red[t] = fmaxf(red[t], red[t + s]);
        __syncthreads();
    }
    mx = red[0];
    __syncthreads();

    float sum = 0.f;
#pragma unroll
    for (int i = 0; i < 8; i++) { float e = __expf(v[i] - mx); v[i] = e; sum += e; }
    red[t] = sum; __syncthreads();
    for (int s = 128; s > 0; s >>= 1) {
        if (t < s) red[t] += red[t + s];
        __syncthreads();
    }
    const float inv = 1.f / red[0];
#pragma unroll
    for (int i = 0; i < 8; i++) p[t + i * 256] = v[i] * inv;
}

// ---------------- launch ----------------
extern "C" void kernel_launch(void* const* d_in, const int* in_sizes, int n_in,
                              void* d_out, int out_size)
{
    const float* query = (const float*)d_in[0];
    const float* keyv  = (const float*)d_in[1];
    const int*   mask  = (const int*)  d_in[2];
    const float* Wq = (const float*)d_in[3];
    const float* bq = (const float*)d_in[4];
    const float* Wk = (const float*)d_in[5];
    const float* bk = (const float*)d_in[6];
    const float* Wv = (const float*)d_in[7];
    const float* bv = (const float*)d_in[8];
    const float* Wo = (const float*)d_in[9];
    const float* bo = (const float*)d_in[10];

    float* out = (float*)d_out;
    const size_t out_elems = (size_t)NB * QL * ED;
    const bool attn_in_out = ((size_t)out_size > out_elems);
    float* attn_ptr = attn_in_out ? (out + out_elems) : nullptr;  // nullptr -> OFF_S

    static bool attr_set = false;
    if (!attr_set) {
        cudaFuncSetAttribute(gemm_mma<1,0,1>, cudaFuncAttributeMaxDynamicSharedMemorySize, SMEM_BYTES);
        cudaFuncSetAttribute(gemm_mma<0,0,0>, cudaFuncAttributeMaxDynamicSharedMemorySize, SMEM_BYTES);
        attr_set = true;
    }

    const int M_ALL = NB * QL;           // 16384
    const float scale = 1.0f / 32.0f;    // 1/sqrt(1024)

    dim3 tposeW(ED / 32, ED / 32, 1);
    dim3 tposeV(ED / 32, KLEN / 32, NB);
    dim3 gProj (ED / BN,   M_ALL / BM, 1);           // (8, 128, 1)
    dim3 gScore(KLEN / BN, QL / BM,    NB);          // (16, 16, 8)
    dim3 gAV   (ED / BN,   QL / BM,    NB);          // (8, 16, 8)

    // 0: weight transposes -> K-major, pre-rounded to tf32
    transpose_mat<<<tposeW, 256>>>(Wq, 0, nullptr, OFF_WQ, ED, ED, 0, 0, 1);
    transpose_mat<<<tposeW, 256>>>(Wk, 0, nullptr, OFF_WK, ED, ED, 0, 0, 1);
    transpose_mat<<<tposeW, 256>>>(Wv, 0, nullptr, OFF_WV, ED, ED, 0, 0, 1);
    transpose_mat<<<tposeW, 256>>>(Wo, 0, nullptr, OFF_WO, ED, ED, 0, 0, 1);

    // 1-3: projections (A raw -> cvt; B pre-rounded; C pre-rounded for GEMM reuse)
    gemm_mma<1,0,1><<<gProj, 128, SMEM_BYTES>>>(query, 0, nullptr, OFF_WQ, bq, nullptr, OFF_Q,
                                                M_ALL, ED, ED, 1.0f, 0, 0, 0);
    gemm_mma<1,0,1><<<gProj, 128, SMEM_BYTES>>>(keyv, 0, nullptr, OFF_WK, bk, nullptr, OFF_K,
                                                M_ALL, ED, ED, 1.0f, 0, 0, 0);
    gemm_mma<1,0,1><<<gProj, 128, SMEM_BYTES>>>(keyv, 0, nullptr, OFF_WV, bv, nullptr, OFF_V,
                                                M_ALL, ED, ED, 1.0f, 0, 0, 0);

    // V^T (already tf32-rounded values)
    transpose_mat<<<tposeV, 256>>>(nullptr, OFF_V, nullptr, OFF_VT,
                                   KLEN, ED, (size_t)KLEN * ED, (size_t)ED * KLEN, 0);

    // 4: scores = scale * Q @ K^T  (both operands pre-rounded -> zero cvt)
    gemm_mma<0,0,0><<<gScore, 128, SMEM_BYTES>>>(nullptr, OFF_Q, nullptr, OFF_K, nullptr,
                                                 attn_ptr, OFF_S,
                                                 QL, KLEN, ED, scale,
                                                 (size_t)QL * ED, (size_t)KLEN * ED,
                                                 (size_t)QL * KLEN);

    // 5: masked softmax in place (attn stays exact fp32 — it is an output)
    softmax_mask_kernel<<<NB * QL, 256>>>(attn_ptr, OFF_S, mask);

    // 6: attended = attn @ V -> reuse OFF_Q, pre-rounded
    gemm_mma<1,0,1><<<gAV, 128, SMEM_BYTES>>>(attn_ptr, OFF_S, nullptr, OFF_VT, nullptr,
                                              nullptr, OFF_Q,
                                              QL, ED, KLEN, 1.0f,
                                              (size_t)QL * KLEN, (size_t)ED * KLEN,
                                              (size_t)QL * ED);

    // 7: out = attended @ Wo + bo (zero cvt)
    gemm_mma<0,0,0><<<gProj, 128, SMEM_BYTES>>>(nullptr, OFF_Q, nullptr, OFF_WO, bo, out, 0,
                                                M_ALL, ED, ED, 1.0f, 0, 0, 0);
}

// round 8
// speedup vs baseline: 6.8798x; 1.0499x over previous
#include <cuda_runtime.h>
#include <math.h>
#include <stdint.h>

#define NB   8
#define QL   2048
#define KLEN 2048
#define ED   1024

// ---------------- scratch arena (floats) ----------------
#define OFF_Q   0ull
#define OFF_K   16777216ull
#define OFF_V   33554432ull
#define OFF_VT  50331648ull
#define OFF_WQ  67108864ull
#define OFF_WK  68157440ull
#define OFF_WV  69206016ull
#define OFF_WO  70254592ull
#define OFF_S   71303168ull
__device__ float g_scratch[104857600ull];   // 400 MB

// ---------------- helpers ----------------
__device__ __forceinline__ uint32_t f2tf32(float f) {
    uint32_t u;
    asm("cvt.rna.tf32.f32 %0, %1;" : "=r"(u) : "f"(f));
    return u;
}
__device__ __forceinline__ uint32_t smem_u32(const void* p) {
    uint32_t a;
    asm("{ .reg .u64 t; cvta.to.shared.u64 t, %1; cvt.u32.u64 %0, t; }" : "=r"(a) : "l"(p));
    return a;
}
__device__ __forceinline__ void cp16(uint32_t s, const void* g) {
    asm volatile("cp.async.cg.shared.global [%0], [%1], 16;" :: "r"(s), "l"(g));
}
__device__ __forceinline__ void mma_tf32(float* d, const uint32_t* a, const uint32_t* b) {
    asm volatile(
        "mma.sync.aligned.m16n8k8.row.col.f32.tf32.tf32.f32 "
        "{%0,%1,%2,%3}, {%4,%5,%6,%7}, {%8,%9}, {%0,%1,%2,%3};"
        : "+f"(d[0]), "+f"(d[1]), "+f"(d[2]), "+f"(d[3])
        : "r"(a[0]), "r"(a[1]), "r"(a[2]), "r"(a[3]), "r"(b[0]), "r"(b[1]));
}

// ---------------- tf32 mma.sync GEMM ----------------
// C[M,N] = scale * A[M,K] @ B[N,K]^T (+bias[n]); A,B K-major row-major.
// k-permutation: logical k t -> physical 2t, t+4 -> 2t+1 (same on A and B),
// so each thread's fragment k-pair is a contiguous float2 in smem (LDS.64).
#define BM 128
#define BN 128
#define BK 32
#define PAD 40                        // LDS.64 conflict-free: bank 8q+2t distinct/half-warp
#define TILE_F (128 * PAD)            // 5120 floats
#define SMEM_BYTES (4 * TILE_F * 4)   // A0 B0 A1 B1 = 81920 B

template<int CA, int CB, int RC>
__global__ void __launch_bounds__(128, 2)
gemm_mma(const float* A, size_t aOff, const float* B, size_t bOff,
         const float* bias, float* C, size_t cOff,
         int M, int N, int Kd, float scale,
         size_t sA, size_t sB, size_t sC)
{
    extern __shared__ float sm[];
    const float* Ap = A ? A : (const float*)(g_scratch + aOff);
    const float* Bp = B ? B : (const float*)(g_scratch + bOff);
    float*       Cp = C ? C : (g_scratch + cOff);
    Ap += (size_t)blockIdx.z * sA;
    Bp += (size_t)blockIdx.z * sB;
    Cp += (size_t)blockIdx.z * sC;

    const int tid  = threadIdx.x;
    const int lane = tid & 31;
    const int wid  = tid >> 5;        // 0..3
    const int wm   = wid >> 1;        // 0..1
    const int wn   = wid & 1;         // 0..1
    const int grp  = lane >> 2;       // 0..7
    const int t4   = lane & 3;        // 0..3
    const int m0   = blockIdx.y * BM;
    const int n0   = blockIdx.x * BN;
    const uint32_t sbase = smem_u32(sm);

    float acc[4][8][4];
#pragma unroll
    for (int a = 0; a < 4; a++)
#pragma unroll
        for (int b = 0; b < 8; b++)
#pragma unroll
            for (int c = 0; c < 4; c++) acc[a][b][c] = 0.f;

    auto issue_tile = [&](int k0, int bufsel) {
        const uint32_t aB = sbase + (bufsel ? 2u * TILE_F * 4u : 0u);
        const uint32_t bB = sbase + (bufsel ? 3u * TILE_F * 4u : TILE_F * 4u);
#pragma unroll
        for (int j = 0; j < 8; j++) {
            int f  = tid + j * 128;       // 0..1023
            int r  = f >> 3;              // 0..127
            int c4 = f & 7;               // 0..7
            uint32_t so = (uint32_t)(r * PAD + c4 * 4) * 4u;
            cp16(aB + so, Ap + (size_t)(m0 + r) * Kd + k0 + c4 * 4);
            cp16(bB + so, Bp + (size_t)(n0 + r) * Kd + k0 + c4 * 4);
        }
        asm volatile("cp.async.commit_group;" ::: "memory");
    };

    issue_tile(0, 0);
    const int NT = Kd / BK;

    for (int i = 0; i < NT; i++) {
        const int buf = i & 1;
        if (i + 1 < NT) {
            issue_tile((i + 1) * BK, buf ^ 1);
            asm volatile("cp.async.wait_group 1;" ::: "memory");
        } else {
            asm volatile("cp.async.wait_group 0;" ::: "memory");
        }
        __syncthreads();

        const float* As = sm + (buf ? 2 * TILE_F : 0);
        const float* Bs = sm + (buf ? 3 * TILE_F : TILE_F);

#pragma unroll
        for (int s = 0; s < 4; s++) {               // 4 x k8 = BK
            uint32_t af[4][4], bf[8][2];
#pragma unroll
            for (int mt = 0; mt < 4; mt++) {
                const int row = wm * 64 + mt * 16 + grp;
                const float2 v0 = *reinterpret_cast<const float2*>(
                    As + row * PAD + s * 8 + t4 * 2);
                const float2 v1 = *reinterpret_cast<const float2*>(
                    As + (row + 8) * PAD + s * 8 + t4 * 2);
                if (CA) {
                    af[mt][0] = f2tf32(v0.x);  // logical k = t4
                    af[mt][1] = f2tf32(v1.x);
                    af[mt][2] = f2tf32(v0.y);  // logical k = t4+4
                    af[mt][3] = f2tf32(v1.y);
                } else {
                    af[mt][0] = __float_as_uint(v0.x);
                    af[mt][1] = __float_as_uint(v1.x);
                    af[mt][2] = __float_as_uint(v0.y);
                    af[mt][3] = __float_as_uint(v1.y);
                }
            }
#pragma unroll
            for (int nt = 0; nt < 8; nt++) {
                const int nr = wn * 64 + nt * 8 + grp;
                const float2 v = *reinterpret_cast<const float2*>(
                    Bs + nr * PAD + s * 8 + t4 * 2);
                if (CB) {
                    bf[nt][0] = f2tf32(v.x);
                    bf[nt][1] = f2tf32(v.y);
                } else {
                    bf[nt][0] = __float_as_uint(v.x);
                    bf[nt][1] = __float_as_uint(v.y);
                }
            }
#pragma unroll
            for (int mt = 0; mt < 4; mt++)
#pragma unroll
                for (int nt = 0; nt < 8; nt++)
                    mma_tf32(acc[mt][nt], af[mt], bf[nt]);
        }
        __syncthreads();
    }

    // ---------------- epilogue ----------------
#pragma unroll
    for (int mt = 0; mt < 4; mt++) {
        const int m = m0 + wm * 64 + mt * 16 + grp;
#pragma unroll
        for (int nt = 0; nt < 8; nt++) {
            const int n = n0 + wn * 64 + nt * 8 + t4 * 2;
            float bx = 0.f, by = 0.f;
            if (bias) {
                const float2 bb = *reinterpret_cast<const float2*>(bias + n);
                bx = bb.x; by = bb.y;
            }
            float2 v0, v1;
            v0.x = acc[mt][nt][0] * scale + bx;
            v0.y = acc[mt][nt][1] * scale + by;
            v1.x = acc[mt][nt][2] * scale + bx;
            v1.y = acc[mt][nt][3] * scale + by;
            if (RC) {
                v0.x = __uint_as_float(f2tf32(v0.x));
                v0.y = __uint_as_float(f2tf32(v0.y));
                v1.x = __uint_as_float(f2tf32(v1.x));
                v1.y = __uint_as_float(f2tf32(v1.y));
            }
            *reinterpret_cast<float2*>(Cp + (size_t)m * N + n) = v0;
            *reinterpret_cast<float2*>(Cp + (size_t)(m + 8) * N + n) = v1;
        }
    }
}

// ---------------- transpose: out[Cc,R] = in[R,Cc]^T (optional tf32 round) ----
__global__ void __launch_bounds__(256)
transpose_mat(const float* in, size_t inOff, float* out, size_t outOff,
              int R, int Cc, size_t sIn, size_t sOut, int doRound)
{
    __shared__ float t[32][33];
    const float* ip = in ? in : (const float*)(g_scratch + inOff);
    float*       op = out ? out : (g_scratch + outOff);
    ip += (size_t)blockIdx.z * sIn;
    op += (size_t)blockIdx.z * sOut;
    const int c0 = blockIdx.x * 32, r0 = blockIdx.y * 32;
    const int tx = threadIdx.x & 31, ty = threadIdx.x >> 5;
#pragma unroll
    for (int i = 0; i < 4; i++) {
        float v = ip[(size_t)(r0 + ty + i * 8) * Cc + c0 + tx];
        if (doRound) v = __uint_as_float(f2tf32(v));
        t[ty + i * 8][tx] = v;
    }
    __syncthreads();
#pragma unroll
    for (int i = 0; i < 4; i++)
        op[(size_t)(c0 + ty + i * 8) * R + r0 + tx] = t[tx][ty + i * 8];
}

// ---------------- masked row softmax (in place) ----------------
__global__ void __launch_bounds__(256)
softmax_mask_kernel(float* att, size_t attOff, const int* __restrict__ mask)
{
    float* base = att ? att : (g_scratch + attOff);
    const size_t row = blockIdx.x;
    float* p = base + row * KLEN;
    const int* mp = mask + row * KLEN;
    const int t = threadIdx.x;
    __shared__ float red[256];

    float v[8];
    float mx = -INFINITY;
#pragma unroll
    for (int i = 0; i < 8; i++) {
        int c = t + i * 256;
        float x = p[c];
        x = mp[c] ? x : -INFINITY;
        v[i] = x;
        mx = fmaxf(mx, x);
    }
    red[t] = mx; __syncthreads();
    for (int s = 128; s > 0; s >>= 1) {
        if (t < s) red[t] = fmaxf(red[t], red[t + s]);
        __syncthreads();
    }
    mx = red[0];
    __syncthreads();

    float sum = 0.f;
#pragma unroll
    for (int i = 0; i < 8; i++) { float e = __expf(v[i] - mx); v[i] = e; sum += e; }
    red[t] = sum; __syncthreads();
    for (int s = 128; s > 0; s >>= 1) {
        if (t < s) red[t] += red[t + s];
        __syncthreads();
    }
    const float inv = 1.f / red[0];
#pragma unroll
    for (int i = 0; i < 8; i++) p[t + i * 256] = v[i] * inv;
}

// ---------------- launch ----------------
extern "C" void kernel_launch(void* const* d_in, const int* in_sizes, int n_in,
                              void* d_out, int out_size)
{
    const float* query = (const float*)d_in[0];
    const float* keyv  = (const float*)d_in[1];
    const int*   mask  = (const int*)  d_in[2];
    const float* Wq = (const float*)d_in[3];
    const float* bq = (const float*)d_in[4];
    const float* Wk = (const float*)d_in[5];
    const float* bk = (const float*)d_in[6];
    const float* Wv = (const float*)d_in[7];
    const float* bv = (const float*)d_in[8];
    const float* Wo = (const float*)d_in[9];
    const float* bo = (const float*)d_in[10];

    float* out = (float*)d_out;
    const size_t out_elems = (size_t)NB * QL * ED;
    const bool attn_in_out = ((size_t)out_size > out_elems);
    float* attn_ptr = attn_in_out ? (out + out_elems) : nullptr;  // nullptr -> OFF_S

    static bool attr_set = false;
    if (!attr_set) {
        cudaFuncSetAttribute(gemm_mma<1,0,1>, cudaFuncAttributeMaxDynamicSharedMemorySize, SMEM_BYTES);
        cudaFuncSetAttribute(gemm_mma<0,0,0>, cudaFuncAttributeMaxDynamicSharedMemorySize, SMEM_BYTES);
        attr_set = true;
    }

    const int M_ALL = NB * QL;           // 16384
    const float scale = 1.0f / 32.0f;    // 1/sqrt(1024)

    dim3 tposeW(ED / 32, ED / 32, 1);
    dim3 tposeV(ED / 32, KLEN / 32, NB);
    dim3 gProj (ED / BN,   M_ALL / BM, 1);           // (8, 128, 1)
    dim3 gScore(KLEN / BN, QL / BM,    NB);          // (16, 16, 8)
    dim3 gAV   (ED / BN,   QL / BM,    NB);          // (8, 16, 8)

    // 0: weight transposes -> K-major, pre-rounded to tf32
    transpose_mat<<<tposeW, 256>>>(Wq, 0, nullptr, OFF_WQ, ED, ED, 0, 0, 1);
    transpose_mat<<<tposeW, 256>>>(Wk, 0, nullptr, OFF_WK, ED, ED, 0, 0, 1);
    transpose_mat<<<tposeW, 256>>>(Wv, 0, nullptr, OFF_WV, ED, ED, 0, 0, 1);
    transpose_mat<<<tposeW, 256>>>(Wo, 0, nullptr, OFF_WO, ED, ED, 0, 0, 1);

    // 1-3: projections (A raw -> cvt; B pre-rounded; C pre-rounded for GEMM reuse)
    gemm_mma<1,0,1><<<gProj, 128, SMEM_BYTES>>>(query, 0, nullptr, OFF_WQ, bq, nullptr, OFF_Q,
                                                M_ALL, ED, ED, 1.0f, 0, 0, 0);
    gemm_mma<1,0,1><<<gProj, 128, SMEM_BYTES>>>(keyv, 0, nullptr, OFF_WK, bk, nullptr, OFF_K,
                                                M_ALL, ED, ED, 1.0f, 0, 0, 0);
    gemm_mma<1,0,1><<<gProj, 128, SMEM_BYTES>>>(keyv, 0, nullptr, OFF_WV, bv, nullptr, OFF_V,
                                                M_ALL, ED, ED, 1.0f, 0, 0, 0);

    // V^T (already tf32-rounded values)
    transpose_mat<<<tposeV, 256>>>(nullptr, OFF_V, nullptr, OFF_VT,
                                   KLEN, ED, (size_t)KLEN * ED, (size_t)ED * KLEN, 0);

    // 4: scores = scale * Q @ K^T  (both operands pre-rounded -> zero cvt)
    gemm_mma<0,0,0><<<gScore, 128, SMEM_BYTES>>>(nullptr, OFF_Q, nullptr, OFF_K, nullptr,
                                                 attn_ptr, OFF_S,
                                                 QL, KLEN, ED, scale,
                                                 (size_t)QL * ED, (size_t)KLEN * ED,
                                                 (size_t)QL * KLEN);

    // 5: masked softmax in place (attn stays exact fp32 — it is an output)
    softmax_mask_kernel<<<NB * QL, 256>>>(attn_ptr, OFF_S, mask);

    // 6: attended = attn @ V -> reuse OFF_Q, pre-rounded
    gemm_mma<1,0,1><<<gAV, 128, SMEM_BYTES>>>(attn_ptr, OFF_S, nullptr, OFF_VT, nullptr,
                                              nullptr, OFF_Q,
                                              QL, ED, KLEN, 1.0f,
                                              (size_t)QL * KLEN, (size_t)ED * KLEN,
                                              (size_t)QL * ED);

    // 7: out = attended @ Wo + bo (zero cvt)
    gemm_mma<0,0,0><<<gProj, 128, SMEM_BYTES>>>(nullptr, OFF_Q, nullptr, OFF_WO, bo, out, 0,
                                                M_ALL, ED, ED, 1.0f, 0, 0, 0);
}

// round 9
// speedup vs baseline: 6.9907x; 1.0161x over previous
#include <cuda_runtime.h>
#include <math.h>
#include <stdint.h>

#define NB   8
#define QL   2048
#define KLEN 2048
#define ED   1024

// ---------------- scratch arena (floats) ----------------
#define OFF_Q   0ull
#define OFF_K   16777216ull
#define OFF_V   33554432ull
#define OFF_VT  50331648ull
#define OFF_WQ  67108864ull
#define OFF_WK  68157440ull
#define OFF_WV  69206016ull
#define OFF_WO  70254592ull
#define OFF_S   71303168ull
__device__ float g_scratch[104857600ull];   // 400 MB

// ---------------- helpers ----------------
__device__ __forceinline__ uint32_t f2tf32(float f) {
    uint32_t u;
    asm("cvt.rna.tf32.f32 %0, %1;" : "=r"(u) : "f"(f));
    return u;
}
__device__ __forceinline__ uint32_t smem_u32(const void* p) {
    uint32_t a;
    asm("{ .reg .u64 t; cvta.to.shared.u64 t, %1; cvt.u32.u64 %0, t; }" : "=r"(a) : "l"(p));
    return a;
}
__device__ __forceinline__ void cp16(uint32_t s, const void* g) {
    asm volatile("cp.async.cg.shared.global [%0], [%1], 16;" :: "r"(s), "l"(g));
}
__device__ __forceinline__ void mma_tf32(float* d, const uint32_t* a, const uint32_t* b) {
    asm volatile(
        "mma.sync.aligned.m16n8k8.row.col.f32.tf32.tf32.f32 "
        "{%0,%1,%2,%3}, {%4,%5,%6,%7}, {%8,%9}, {%0,%1,%2,%3};"
        : "+f"(d[0]), "+f"(d[1]), "+f"(d[2]), "+f"(d[3])
        : "r"(a[0]), "r"(a[1]), "r"(a[2]), "r"(a[3]), "r"(b[0]), "r"(b[1]));
}

// ---------------- tf32 mma.sync GEMM ----------------
// C[M,N] = scale * A[M,K] @ B[N,K]^T (+bias[n]); A,B K-major row-major.
// smem row = 32 floats (no pad); 16B chunk c of row r stored at chunk c ^ ((r&1)<<2).
// Fragment float4 at chunk (s2*4 + t4) covers that thread's k-pairs for TWO
// consecutive k8-steps; the implied k relabeling is identical on A and B, so
// the GEMM result is exact.
#define BM 128
#define BN 128
#define BK 32
#define TILE_F 4096                       // 128 rows x 32 floats = 16 KB
#define NSTAGE 3
#define STAGE_F (2 * TILE_F)              // A then B
#define SMEM_BYTES (NSTAGE * STAGE_F * 4) // 98304 B

template<int CA, int CB, int RC>
__global__ void __launch_bounds__(128, 2)
gemm_mma(const float* A, size_t aOff, const float* B, size_t bOff,
         const float* bias, float* C, size_t cOff,
         int M, int N, int Kd, float scale,
         size_t sA, size_t sB, size_t sC)
{
    extern __shared__ float sm[];
    const float* Ap = A ? A : (const float*)(g_scratch + aOff);
    const float* Bp = B ? B : (const float*)(g_scratch + bOff);
    float*       Cp = C ? C : (g_scratch + cOff);
    Ap += (size_t)blockIdx.z * sA;
    Bp += (size_t)blockIdx.z * sB;
    Cp += (size_t)blockIdx.z * sC;

    const int tid  = threadIdx.x;
    const int lane = tid & 31;
    const int wid  = tid >> 5;        // 0..3
    const int wm   = wid >> 1;        // 0..1
    const int wn   = wid & 1;         // 0..1
    const int grp  = lane >> 2;       // 0..7
    const int t4   = lane & 3;        // 0..3
    const int m0   = blockIdx.y * BM;
    const int n0   = blockIdx.x * BN;
    const uint32_t sbase = smem_u32(sm);

    float acc[4][8][4];
#pragma unroll
    for (int a = 0; a < 4; a++)
#pragma unroll
        for (int b = 0; b < 8; b++)
#pragma unroll
            for (int c = 0; c < 4; c++) acc[a][b][c] = 0.f;

    // loader: per operand 128 rows x 8 chunks; swizzled store
    auto issue_tile = [&](int k0, int stg) {
        const uint32_t aB = sbase + (uint32_t)stg * STAGE_F * 4u;
        const uint32_t bB = aB + TILE_F * 4u;
#pragma unroll
        for (int j = 0; j < 8; j++) {
            int f  = tid + j * 128;       // 0..1023
            int r  = f >> 3;              // 0..127
            int c4 = f & 7;               // 0..7
            uint32_t sc = (uint32_t)(c4 ^ ((r & 1) << 2));
            uint32_t so = (uint32_t)(r * 32) * 4u + sc * 16u;
            cp16(aB + so, Ap + (size_t)(m0 + r) * Kd + k0 + c4 * 4);
            cp16(bB + so, Bp + (size_t)(n0 + r) * Kd + k0 + c4 * 4);
        }
        asm volatile("cp.async.commit_group;" ::: "memory");
    };

    const int NT = Kd / BK;
    issue_tile(0, 0);
    issue_tile(BK, 1);

    for (int i = 0; i < NT; i++) {
        if (i + 1 < NT) {
            asm volatile("cp.async.wait_group 1;" ::: "memory");
        } else {
            asm volatile("cp.async.wait_group 0;" ::: "memory");
        }
        __syncthreads();
        if (i + 2 < NT) issue_tile((i + 2) * BK, (i + 2) % NSTAGE);

        const int stg = i % NSTAGE;
        const float* As = sm + stg * STAGE_F;
        const float* Bs = As + TILE_F;

#pragma unroll
        for (int s2 = 0; s2 < 2; s2++) {            // each s2 = two k8 steps
            float4 av[4][2], bv[8];
#pragma unroll
            for (int mt = 0; mt < 4; mt++) {
                const int r0 = wm * 64 + mt * 16 + grp;
                const int r1 = r0 + 8;
                const uint32_t ch0 = (uint32_t)((s2 * 4 + t4) ^ ((r0 & 1) << 2));
                const uint32_t ch1 = (uint32_t)((s2 * 4 + t4) ^ ((r1 & 1) << 2));
                av[mt][0] = *reinterpret_cast<const float4*>(As + r0 * 32 + ch0 * 4);
                av[mt][1] = *reinterpret_cast<const float4*>(As + r1 * 32 + ch1 * 4);
            }
#pragma unroll
            for (int nt = 0; nt < 8; nt++) {
                const int nr = wn * 64 + nt * 8 + grp;
                const uint32_t ch = (uint32_t)((s2 * 4 + t4) ^ ((nr & 1) << 2));
                bv[nt] = *reinterpret_cast<const float4*>(Bs + nr * 32 + ch * 4);
            }
            // sub-step 0: (x, y) ; sub-step 1: (z, w)
#pragma unroll
            for (int h = 0; h < 2; h++) {
                uint32_t af[4][4], bf[8][2];
#pragma unroll
                for (int mt = 0; mt < 4; mt++) {
                    const float lo0 = h ? av[mt][0].z : av[mt][0].x;
                    const float hi0 = h ? av[mt][0].w : av[mt][0].y;
                    const float lo1 = h ? av[mt][1].z : av[mt][1].x;
                    const float hi1 = h ? av[mt][1].w : av[mt][1].y;
                    if (CA) {
                        af[mt][0] = f2tf32(lo0); af[mt][1] = f2tf32(lo1);
                        af[mt][2] = f2tf32(hi0); af[mt][3] = f2tf32(hi1);
                    } else {
                        af[mt][0] = __float_as_uint(lo0); af[mt][1] = __float_as_uint(lo1);
                        af[mt][2] = __float_as_uint(hi0); af[mt][3] = __float_as_uint(hi1);
                    }
                }
#pragma unroll
                for (int nt = 0; nt < 8; nt++) {
                    const float lo = h ? bv[nt].z : bv[nt].x;
                    const float hi = h ? bv[nt].w : bv[nt].y;
                    if (CB) {
                        bf[nt][0] = f2tf32(lo); bf[nt][1] = f2tf32(hi);
                    } else {
                        bf[nt][0] = __float_as_uint(lo); bf[nt][1] = __float_as_uint(hi);
                    }
                }
#pragma unroll
                for (int mt = 0; mt < 4; mt++)
#pragma unroll
                    for (int nt = 0; nt < 8; nt++)
                        mma_tf32(acc[mt][nt], af[mt], bf[nt]);
            }
        }
    }

    // ---------------- epilogue ----------------
#pragma unroll
    for (int mt = 0; mt < 4; mt++) {
        const int m = m0 + wm * 64 + mt * 16 + grp;
#pragma unroll
        for (int nt = 0; nt < 8; nt++) {
            const int n = n0 + wn * 64 + nt * 8 + t4 * 2;
            float bx = 0.f, by = 0.f;
            if (bias) {
                const float2 bb = *reinterpret_cast<const float2*>(bias + n);
                bx = bb.x; by = bb.y;
            }
            float2 v0, v1;
            v0.x = acc[mt][nt][0] * scale + bx;
            v0.y = acc[mt][nt][1] * scale + by;
            v1.x = acc[mt][nt][2] * scale + bx;
            v1.y = acc[mt][nt][3] * scale + by;
            if (RC) {
                v0.x = __uint_as_float(f2tf32(v0.x));
                v0.y = __uint_as_float(f2tf32(v0.y));
                v1.x = __uint_as_float(f2tf32(v1.x));
                v1.y = __uint_as_float(f2tf32(v1.y));
            }
            *reinterpret_cast<float2*>(Cp + (size_t)m * N + n) = v0;
            *reinterpret_cast<float2*>(Cp + (size_t)(m + 8) * N + n) = v1;
        }
    }
}

// ---------------- transpose: out[Cc,R] = in[R,Cc]^T (optional tf32 round) ----
__global__ void __launch_bounds__(256)
transpose_mat(const float* in, size_t inOff, float* out, size_t outOff,
              int R, int Cc, size_t sIn, size_t sOut, int doRound)
{
    __shared__ float t[32][33];
    const float* ip = in ? in : (const float*)(g_scratch + inOff);
    float*       op = out ? out : (g_scratch + outOff);
    ip += (size_t)blockIdx.z * sIn;
    op += (size_t)blockIdx.z * sOut;
    const int c0 = blockIdx.x * 32, r0 = blockIdx.y * 32;
    const int tx = threadIdx.x & 31, ty = threadIdx.x >> 5;
#pragma unroll
    for (int i = 0; i < 4; i++) {
        float v = ip[(size_t)(r0 + ty + i * 8) * Cc + c0 + tx];
        if (doRound) v = __uint_as_float(f2tf32(v));
        t[ty + i * 8][tx] = v;
    }
    __syncthreads();
#pragma unroll
    for (int i = 0; i < 4; i++)
        op[(size_t)(c0 + ty + i * 8) * R + r0 + tx] = t[tx][ty + i * 8];
}

// ---------------- masked row softmax (in place) ----------------
__global__ void __launch_bounds__(256)
softmax_mask_kernel(float* att, size_t attOff, const int* __restrict__ mask)
{
    float* base = att ? att : (g_scratch + attOff);
    const size_t row = blockIdx.x;
    float* p = base + row * KLEN;
    const int* mp = mask + row * KLEN;
    const int t = threadIdx.x;
    __shared__ float red[256];

    float v[8];
    float mx = -INFINITY;
#pragma unroll
    for (int i = 0; i < 8; i++) {
        int c = t + i * 256;
        float x = p[c];
        x = mp[c] ? x : -INFINITY;
        v[i] = x;
        mx = fmaxf(mx, x);
    }
    red[t] = mx; __syncthreads();
    for (int s = 128; s > 0; s >>= 1) {
        if (t < s) red[t] = fmaxf(red[t], red[t + s]);
        __syncthreads();
    }
    mx = red[0];
    __syncthreads();

    float sum = 0.f;
#pragma unroll
    for (int i = 0; i < 8; i++) { float e = __expf(v[i] - mx); v[i] = e; sum += e; }
    red[t] = sum; __syncthreads();
    for (int s = 128; s > 0; s >>= 1) {
        if (t < s) red[t] += red[t + s];
        __syncthreads();
    }
    const float inv = 1.f / red[0];
#pragma unroll
    for (int i = 0; i < 8; i++) p[t + i * 256] = v[i] * inv;
}

// ---------------- launch ----------------
extern "C" void kernel_launch(void* const* d_in, const int* in_sizes, int n_in,
                              void* d_out, int out_size)
{
    const float* query = (const float*)d_in[0];
    const float* keyv  = (const float*)d_in[1];
    const int*   mask  = (const int*)  d_in[2];
    const float* Wq = (const float*)d_in[3];
    const float* bq = (const float*)d_in[4];
    const float* Wk = (const float*)d_in[5];
    const float* bk = (const float*)d_in[6];
    const float* Wv = (const float*)d_in[7];
    const float* bv = (const float*)d_in[8];
    const float* Wo = (const float*)d_in[9];
    const float* bo = (const float*)d_in[10];

    float* out = (float*)d_out;
    const size_t out_elems = (size_t)NB * QL * ED;
    const bool attn_in_out = ((size_t)out_size > out_elems);
    float* attn_ptr = attn_in_out ? (out + out_elems) : nullptr;  // nullptr -> OFF_S

    static bool attr_set = false;
    if (!attr_set) {
        cudaFuncSetAttribute(gemm_mma<1,0,1>, cudaFuncAttributeMaxDynamicSharedMemorySize, SMEM_BYTES);
        cudaFuncSetAttribute(gemm_mma<0,0,0>, cudaFuncAttributeMaxDynamicSharedMemorySize, SMEM_BYTES);
        attr_set = true;
    }

    const int M_ALL = NB * QL;           // 16384
    const float scale = 1.0f / 32.0f;    // 1/sqrt(1024)

    dim3 tposeW(ED / 32, ED / 32, 1);
    dim3 tposeV(ED / 32, KLEN / 32, NB);
    dim3 gProj (ED / BN,   M_ALL / BM, 1);           // (8, 128, 1)
    dim3 gScore(KLEN / BN, QL / BM,    NB);          // (16, 16, 8)
    dim3 gAV   (ED / BN,   QL / BM,    NB);          // (8, 16, 8)

    // 0: weight transposes -> K-major, pre-rounded to tf32
    transpose_mat<<<tposeW, 256>>>(Wq, 0, nullptr, OFF_WQ, ED, ED, 0, 0, 1);
    transpose_mat<<<tposeW, 256>>>(Wk, 0, nullptr, OFF_WK, ED, ED, 0, 0, 1);
    transpose_mat<<<tposeW, 256>>>(Wv, 0, nullptr, OFF_WV, ED, ED, 0, 0, 1);
    transpose_mat<<<tposeW, 256>>>(Wo, 0, nullptr, OFF_WO, ED, ED, 0, 0, 1);

    // 1-3: projections (A raw -> cvt; B pre-rounded; C pre-rounded for GEMM reuse)
    gemm_mma<1,0,1><<<gProj, 128, SMEM_BYTES>>>(query, 0, nullptr, OFF_WQ, bq, nullptr, OFF_Q,
                                                M_ALL, ED, ED, 1.0f, 0, 0, 0);
    gemm_mma<1,0,1><<<gProj, 128, SMEM_BYTES>>>(keyv, 0, nullptr, OFF_WK, bk, nullptr, OFF_K,
                                                M_ALL, ED, ED, 1.0f, 0, 0, 0);
    gemm_mma<1,0,1><<<gProj, 128, SMEM_BYTES>>>(keyv, 0, nullptr, OFF_WV, bv, nullptr, OFF_V,
                                                M_ALL, ED, ED, 1.0f, 0, 0, 0);

    // V^T (already tf32-rounded values)
    transpose_mat<<<tposeV, 256>>>(nullptr, OFF_V, nullptr, OFF_VT,
                                   KLEN, ED, (size_t)KLEN * ED, (size_t)ED * KLEN, 0);

    // 4: scores = scale * Q @ K^T  (both operands pre-rounded -> zero cvt)
    gemm_mma<0,0,0><<<gScore, 128, SMEM_BYTES>>>(nullptr, OFF_Q, nullptr, OFF_K, nullptr,
                                                 attn_ptr, OFF_S,
                                                 QL, KLEN, ED, scale,
                                                 (size_t)QL * ED, (size_t)KLEN * ED,
                                                 (size_t)QL * KLEN);

    // 5: masked softmax in place (attn stays exact fp32 — it is an output)
    softmax_mask_kernel<<<NB * QL, 256>>>(attn_ptr, OFF_S, mask);

    // 6: attended = attn @ V -> reuse OFF_Q, pre-rounded
    gemm_mma<1,0,1><<<gAV, 128, SMEM_BYTES>>>(attn_ptr, OFF_S, nullptr, OFF_VT, nullptr,
                                              nullptr, OFF_Q,
                                              QL, ED, KLEN, 1.0f,
                                              (size_t)QL * KLEN, (size_t)ED * KLEN,
                                              (size_t)QL * ED);

    // 7: out = attended @ Wo + bo (zero cvt)
    gemm_mma<0,0,0><<<gProj, 128, SMEM_BYTES>>>(nullptr, OFF_Q, nullptr, OFF_WO, bo, out, 0,
                                                M_ALL, ED, ED, 1.0f, 0, 0, 0);
}

// round 13
// speedup vs baseline: 12.1886x; 1.7435x over previous
#include <cuda_runtime.h>
#include <cuda_fp16.h>
#include <math.h>
#include <stdint.h>

#define NB   8
#define QL   2048
#define KLEN 2048
#define ED   1024

// ---------------- scratch arena ----------------
// First region is an fp16 arena (offsets in halves), tail is fp32 (offsets in floats).
#define H_QIN  0ull
#define H_KVIN 16777216ull
#define H_WQ   33554432ull
#define H_WK   34603008ull
#define H_WV   35651584ull
#define H_WO   36700160ull
#define H_Q    37748736ull
#define H_K    54525952ull
#define H_V    71303168ull
#define H_VT   88080384ull
#define H_ATT  104857600ull      // 32M halves
#define H_ATTD 138412032ull      // ends 155189248 halves = 77,594,624 floats
#define OFF_S  79691776ull       // fp32 scores fallback (32M floats)
__device__ float g_scratch[125829120ull];   // 480 MB

// ---------------- helpers ----------------
__device__ __forceinline__ uint32_t smem_u32(const void* p) {
    uint32_t a;
    asm("{ .reg .u64 t; cvta.to.shared.u64 t, %1; cvt.u32.u64 %0, t; }" : "=r"(a) : "l"(p));
    return a;
}
__device__ __forceinline__ void cp16(uint32_t s, const void* g) {
    asm volatile("cp.async.cg.shared.global [%0], [%1], 16;" :: "r"(s), "l"(g));
}
__device__ __forceinline__ void mma_f16(float* d, uint32_t a0, uint32_t a1,
                                        uint32_t a2, uint32_t a3,
                                        uint32_t b0, uint32_t b1) {
    asm volatile(
        "mma.sync.aligned.m16n8k16.row.col.f32.f16.f16.f32 "
        "{%0,%1,%2,%3}, {%4,%5,%6,%7}, {%8,%9}, {%0,%1,%2,%3};"
        : "+f"(d[0]), "+f"(d[1]), "+f"(d[2]), "+f"(d[3])
        : "r"(a0), "r"(a1), "r"(a2), "r"(a3), "r"(b0), "r"(b1));
}

// ---------------- fp16 mma.sync GEMM ----------------
// C[M,N] = scale * A[M,K] @ B[N,K]^T (+bias[n]); A,B fp16 K-major in half arena.
// k-permutation: within each 16-k group, thread t4's logical k {2t,2t+1,2t+8,2t+9}
// live at physical halves {4t..4t+3} (one 8B load). Same relabeling on A and B
// => exact same dot products.
#define BM 128
#define BN 128
#define BKH 64                       // k-halves per tile
#define ROWB 160u                    // bytes per smem row (128 data + 32 pad)
#define TILEB (128u * ROWB)          // 20480
#define STAGEB (2u * TILEB)          // A then B
#define SMEM_BYTES (2 * (int)STAGEB) // 81920

template<int OUTH>
__global__ void __launch_bounds__(128, 2)
gemm_h(size_t aOff, size_t bOff, const float* bias,
       float* Cf, size_t cOff, int M, int N, int Kd, float scale,
       size_t sA, size_t sB, size_t sC)
{
    extern __shared__ char smc[];
    const __half* Ap = (const __half*)g_scratch + aOff + (size_t)blockIdx.z * sA;
    const __half* Bp = (const __half*)g_scratch + bOff + (size_t)blockIdx.z * sB;

    const int tid  = threadIdx.x;
    const int lane = tid & 31;
    const int wid  = tid >> 5;
    const int wm   = wid >> 1;        // 0..1
    const int wn   = wid & 1;         // 0..1
    const int grp  = lane >> 2;       // 0..7
    const int t4   = lane & 3;        // 0..3
    const int m0   = blockIdx.y * BM;
    const int n0   = blockIdx.x * BN;
    const uint32_t sbase = smem_u32(smc);

    float acc[4][8][4];
#pragma unroll
    for (int a = 0; a < 4; a++)
#pragma unroll
        for (int b = 0; b < 8; b++)
#pragma unroll
            for (int c = 0; c < 4; c++) acc[a][b][c] = 0.f;

    auto issue_tile = [&](int k0, int stg) {
        const uint32_t aB = sbase + (uint32_t)stg * STAGEB;
        const uint32_t bB = aB + TILEB;
#pragma unroll
        for (int j = 0; j < 8; j++) {
            int f  = tid + j * 128;       // 0..1023
            int r  = f >> 3;              // 0..127
            int c  = f & 7;               // 16B chunk = 8 halves
            cp16(aB + (uint32_t)r * ROWB + (uint32_t)c * 16u,
                 Ap + (size_t)(m0 + r) * Kd + k0 + c * 8);
            cp16(bB + (uint32_t)r * ROWB + (uint32_t)c * 16u,
                 Bp + (size_t)(n0 + r) * Kd + k0 + c * 8);
        }
        asm volatile("cp.async.commit_group;" ::: "memory");
    };

    const int NT = Kd / BKH;
    issue_tile(0, 0);

    for (int i = 0; i < NT; i++) {
        if (i + 1 < NT) {
            issue_tile((i + 1) * BKH, (i + 1) & 1);
            asm volatile("cp.async.wait_group 1;" ::: "memory");
        } else {
            asm volatile("cp.async.wait_group 0;" ::: "memory");
        }
        __syncthreads();

        const char* As = smc + (i & 1) * STAGEB;
        const char* Bs = As + TILEB;

#pragma unroll
        for (int s = 0; s < 4; s++) {            // 4 x k16 = BKH
            uint2 avLo[4], avHi[4], bv[8];
#pragma unroll
            for (int mt = 0; mt < 4; mt++) {
                const int row = wm * 64 + mt * 16 + grp;
                avLo[mt] = *reinterpret_cast<const uint2*>(
                    As + (size_t)row * ROWB + s * 32 + t4 * 8);
                avHi[mt] = *reinterpret_cast<const uint2*>(
                    As + (size_t)(row + 8) * ROWB + s * 32 + t4 * 8);
            }
#pragma unroll
            for (int nt = 0; nt < 8; nt++) {
                const int nr = wn * 64 + nt * 8 + grp;
                bv[nt] = *reinterpret_cast<const uint2*>(
                    Bs + (size_t)nr * ROWB + s * 32 + t4 * 8);
            }
#pragma unroll
            for (int mt = 0; mt < 4; mt++)
#pragma unroll
                for (int nt = 0; nt < 8; nt++)
                    mma_f16(acc[mt][nt],
                            avLo[mt].x, avHi[mt].x, avLo[mt].y, avHi[mt].y,
                            bv[nt].x, bv[nt].y);
        }
        __syncthreads();
    }

    // ---------------- epilogue ----------------
    __half* Ch = (__half*)g_scratch + cOff + (size_t)blockIdx.z * sC;
    float* Cp = nullptr;
    if (!OUTH) Cp = (Cf ? Cf : (g_scratch + cOff)) + (size_t)blockIdx.z * sC;

#pragma unroll
    for (int mt = 0; mt < 4; mt++) {
        const int m = m0 + wm * 64 + mt * 16 + grp;
#pragma unroll
        for (int nt = 0; nt < 8; nt++) {
            const int n = n0 + wn * 64 + nt * 8 + t4 * 2;
            float bx = 0.f, by = 0.f;
            if (bias) {
                const float2 bb = *reinterpret_cast<const float2*>(bias + n);
                bx = bb.x; by = bb.y;
            }
            const float v00 = acc[mt][nt][0] * scale + bx;
            const float v01 = acc[mt][nt][1] * scale + by;
            const float v10 = acc[mt][nt][2] * scale + bx;
            const float v11 = acc[mt][nt][3] * scale + by;
            if (OUTH) {
                *reinterpret_cast<__half2*>(Ch + (size_t)m * N + n) =
                    __floats2half2_rn(v00, v01);
                *reinterpret_cast<__half2*>(Ch + (size_t)(m + 8) * N + n) =
                    __floats2half2_rn(v10, v11);
            } else {
                *reinterpret_cast<float2*>(Cp + (size_t)m * N + n) = make_float2(v00, v01);
                *reinterpret_cast<float2*>(Cp + (size_t)(m + 8) * N + n) = make_float2(v10, v11);
            }
        }
    }
}

// ---------------- fp32 -> fp16 elementwise ----------------
__global__ void __launch_bounds__(256)
cvt_f2h(const float* __restrict__ in, size_t hOff, size_t n)
{
    const size_t i = ((size_t)blockIdx.x * 256 + threadIdx.x) * 4;
    if (i >= n) return;
    const float4 v = *reinterpret_cast<const float4*>(in + i);
    __half2 h0 = __floats2half2_rn(v.x, v.y);
    __half2 h1 = __floats2half2_rn(v.z, v.w);
    __half2* dst = reinterpret_cast<__half2*>((__half*)g_scratch + hOff + i);
    dst[0] = h0;
    dst[1] = h1;
}

// ---------------- fp32 -> fp16 transpose (weights) ----------------
__global__ void __launch_bounds__(256)
cvtT_f2h(const float* __restrict__ in, size_t hOff, int R, int Cc)
{
    __shared__ float t[32][33];
    const int c0 = blockIdx.x * 32, r0 = blockIdx.y * 32;
    const int tx = threadIdx.x & 31, ty = threadIdx.x >> 5;
#pragma unroll
    for (int i = 0; i < 4; i++)
        t[ty + i * 8][tx] = in[(size_t)(r0 + ty + i * 8) * Cc + c0 + tx];
    __syncthreads();
    __half* op = (__half*)g_scratch + hOff;
#pragma unroll
    for (int i = 0; i < 4; i++)
        op[(size_t)(c0 + ty + i * 8) * R + r0 + tx] = __float2half(t[tx][ty + i * 8]);
}

// ---------------- fp16 -> fp16 transpose (V -> VT per batch) ----------------
__global__ void __launch_bounds__(256)
transpose_h(size_t inOff, size_t outOff, int R, int Cc, size_t sIn, size_t sOut)
{
    __shared__ __half t[32][34];
    const __half* ip = (const __half*)g_scratch + inOff + (size_t)blockIdx.z * sIn;
    __half*       op = (__half*)g_scratch + outOff + (size_t)blockIdx.z * sOut;
    const int c0 = blockIdx.x * 32, r0 = blockIdx.y * 32;
    const int tx = threadIdx.x & 31, ty = threadIdx.x >> 5;
#pragma unroll
    for (int i = 0; i < 4; i++)
        t[ty + i * 8][tx] = ip[(size_t)(r0 + ty + i * 8) * Cc + c0 + tx];
    __syncthreads();
#pragma unroll
    for (int i = 0; i < 4; i++)
        op[(size_t)(c0 + ty + i * 8) * R + r0 + tx] = t[tx][ty + i * 8];
}

// ---------------- masked row softmax: fp32 in place + fp16 copy ----------------
__global__ void __launch_bounds__(256)
softmax_mask_kernel(float* att, size_t attOff, const int* __restrict__ mask)
{
    float* base = att ? att : (g_scratch + attOff);
    const size_t row = blockIdx.x;
    float* p = base + row * KLEN;
    __half* ph = (__half*)g_scratch + H_ATT + row * KLEN;
    const int* mp = mask + row * KLEN;
    const int t = threadIdx.x;
    __shared__ float red[256];

    float v[8];
    float mx = -INFINITY;
#pragma unroll
    for (int i = 0; i < 8; i++) {
        int c = t + i * 256;
        float x = p[c];
        x = mp[c] ? x : -INFINITY;
        v[i] = x;
        mx = fmaxf(mx, x);
    }
    red[t] = mx; __syncthreads();
    for (int s = 128; s > 0; s >>= 1) {
        if (t < s) red[t] = fmaxf(red[t], red[t + s]);
        __syncthreads();
    }
    mx = red[0];
    __syncthreads();

    float sum = 0.f;
#pragma unroll
    for (int i = 0; i < 8; i++) { float e = __expf(v[i] - mx); v[i] = e; sum += e; }
    red[t] = sum; __syncthreads();
    for (int s = 128; s > 0; s >>= 1) {
        if (t < s) red[t] += red[t + s];
        __syncthreads();
    }
    const float inv = 1.f / red[0];
#pragma unroll
    for (int i = 0; i < 8; i++) {
        const int c = t + i * 256;
        const float val = v[i] * inv;
        p[c] = val;
        ph[c] = __float2half(val);
    }
}

// ---------------- launch ----------------
extern "C" void kernel_launch(void* const* d_in, const int* in_sizes, int n_in,
                              void* d_out, int out_size)
{
    const float* query = (const float*)d_in[0];
    const float* keyv  = (const float*)d_in[1];
    const int*   mask  = (const int*)  d_in[2];
    const float* Wq = (const float*)d_in[3];
    const float* bq = (const float*)d_in[4];
    const float* Wk = (const float*)d_in[5];
    const float* bk = (const float*)d_in[6];
    const float* Wv = (const float*)d_in[7];
    const float* bv = (const float*)d_in[8];
    const float* Wo = (const float*)d_in[9];
    const float* bo = (const float*)d_in[10];

    float* out = (float*)d_out;
    const size_t out_elems = (size_t)NB * QL * ED;
    const bool attn_in_out = ((size_t)out_size > out_elems);
    float* attn_ptr = attn_in_out ? (out + out_elems) : nullptr;  // nullptr -> OFF_S

    static bool attr_set = false;
    if (!attr_set) {
        cudaFuncSetAttribute(gemm_h<0>, cudaFuncAttributeMaxDynamicSharedMemorySize, SMEM_BYTES);
        cudaFuncSetAttribute(gemm_h<1>, cudaFuncAttributeMaxDynamicSharedMemorySize, SMEM_BYTES);
        attr_set = true;
    }

    const int M_ALL = NB * QL;           // 16384
    const float scale = 1.0f / 32.0f;    // 1/sqrt(1024)
    const size_t nIn = (size_t)M_ALL * ED;  // 16M elements

    dim3 cvtG((unsigned)((nIn / 4 + 255) / 256));
    dim3 tposeW(ED / 32, ED / 32, 1);
    dim3 tposeV(ED / 32, KLEN / 32, NB);
    dim3 gProj (ED / BN,   M_ALL / BM, 1);           // (8, 128, 1)
    dim3 gScore(KLEN / BN, QL / BM,    NB);          // (16, 16, 8)
    dim3 gAV   (ED / BN,   QL / BM,    NB);          // (8, 16, 8)

    // 0: convert inputs + weights to fp16 (weights also transposed to K-major)
    cvt_f2h<<<cvtG, 256>>>(query, H_QIN, nIn);
    cvt_f2h<<<cvtG, 256>>>(keyv,  H_KVIN, nIn);
    cvtT_f2h<<<tposeW, 256>>>(Wq, H_WQ, ED, ED);
    cvtT_f2h<<<tposeW, 256>>>(Wk, H_WK, ED, ED);
    cvtT_f2h<<<tposeW, 256>>>(Wv, H_WV, ED, ED);
    cvtT_f2h<<<tposeW, 256>>>(Wo, H_WO, ED, ED);

    // 1-3: projections -> fp16 Q/K/V
    gemm_h<1><<<gProj, 128, SMEM_BYTES>>>(H_QIN, H_WQ, bq, nullptr, H_Q,
                                          M_ALL, ED, ED, 1.0f, 0, 0, 0);
    gemm_h<1><<<gProj, 128, SMEM_BYTES>>>(H_KVIN, H_WK, bk, nullptr, H_K,
                                          M_ALL, ED, ED, 1.0f, 0, 0, 0);
    gemm_h<1><<<gProj, 128, SMEM_BYTES>>>(H_KVIN, H_WV, bv, nullptr, H_V,
                                          M_ALL, ED, ED, 1.0f, 0, 0, 0);

    // V^T per batch (fp16)
    transpose_h<<<tposeV, 256>>>(H_V, H_VT, KLEN, ED,
                                 (size_t)KLEN * ED, (size_t)ED * KLEN);

    // 4: scores = scale * Q @ K^T -> fp32 attn
    gemm_h<0><<<gScore, 128, SMEM_BYTES>>>(H_Q, H_K, nullptr, attn_ptr, OFF_S,
                                           QL, KLEN, ED, scale,
                                           (size_t)QL * ED, (size_t)KLEN * ED,
                                           (size_t)QL * KLEN);

    // 5: masked softmax (fp32 in place, fp16 copy to H_ATT)
    softmax_mask_kernel<<<NB * QL, 256>>>(attn_ptr, OFF_S, mask);

    // 6: attended = attn @ V -> fp16 H_ATTD
    gemm_h<1><<<gAV, 128, SMEM_BYTES>>>(H_ATT, H_VT, nullptr, nullptr, H_ATTD,
                                        QL, ED, KLEN, 1.0f,
                                        (size_t)QL * KLEN, (size_t)ED * KLEN,
                                        (size_t)QL * ED);

    // 7: out = attended @ Wo + bo -> fp32 d_out
    gemm_h<0><<<gProj, 128, SMEM_BYTES>>>(H_ATTD, H_WO, bo, out, 0,
                                          M_ALL, ED, ED, 1.0f, 0, 0, 0);
}